// round 15
// baseline (speedup 1.0000x reference)
#include <cuda_runtime.h>
#include <math.h>

#define BB    16
#define LL    600
#define CC    256
#define OUTS  6000
#define NBLK  10
#define CONDN 256
#define LT    16      // conv output cols per block (38 tiles, last ragged)
#define NLT   38
#define OT    20      // align o's per block (6000 = 300*20)
#define NCCBN 32
#define NPMAX 304
#define BCL   (BB*CC*LL)

// prep kernel partition (wt1 + gamma/beta; conv weights in k_wtT)
#define PREP_WT1_BLOCKS  ((CC*CC) / 256)                    // 256
#define PREP_GB_BLOCKS   (NCCBN * BB)                       // 512
#define PREP_TOTAL       (PREP_WT1_BLOCKS + PREP_GB_BLOCKS)

// ----------------- static device scratch (no allocations allowed) -----------------
__device__ __align__(16) float g_x[BCL];
__device__ __align__(16) float g_t0[BCL];
__device__ __align__(16) float g_t1[BCL];
__device__ __align__(16) float2 g_wt2[NBLK*3*5*CC*CC];  // [conv][ci][k][co] splatted (w,w)
__device__ __align__(16) float2 g_wt1s[CC*CC];          // tl conv1 [ci][co] splatted
__device__ __align__(16) float2 g_gb[NCCBN*BB*CC];      // (gamma, beta) interleaved
__device__ __align__(16) double2 g_part[CC*NPMAX];      // per-(channel, block) partial (sum, sumsq)
__device__ __align__(8) float2 g_mur[CC];               // (mu, rstd) interleaved
__device__ float g_centers[BB*LL];
__device__ __align__(16) float g_featsT[BB*LL*CC];

// ----------------- f32x2 helpers -----------------
__device__ __forceinline__ unsigned long long pk(float lo, float hi) {
    unsigned long long r;
    asm("mov.b64 %0, {%1,%2};" : "=l"(r) : "f"(lo), "f"(hi));
    return r;
}
__device__ __forceinline__ float2 upk(unsigned long long v) {
    float2 r;
    asm("mov.b64 {%0,%1}, %2;" : "=f"(r.x), "=f"(r.y) : "l"(v));
    return r;
}
__device__ __forceinline__ void fma2(unsigned long long& d, unsigned long long a,
                                     unsigned long long b) {
    asm("fma.rn.f32x2 %0, %1, %2, %0;" : "+l"(d) : "l"(a), "l"(b));
}
__device__ __forceinline__ unsigned long long add2(unsigned long long a,
                                                   unsigned long long b) {
    unsigned long long r;
    asm("add.rn.f32x2 %0, %1, %2;" : "=l"(r) : "l"(a), "l"(b));
    return r;
}

// compensated accumulate: s += (a*b) exactly split via TwoProdFMA + branchless 2Sum
__device__ __forceinline__ void comp_fma(float a, float b, float& s, float& c) {
    float p = __fmul_rn(a, b);
    float e = fmaf(a, b, -p);          // exact product error
    float t  = s + p;
    float bp = t - s;
    c += (s - (t - bp)) + (p - bp);    // 2Sum error
    c += e;
    s = t;
}

// ----------------- conv weight transpose (coalesced both sides via smem tile) -----------------
// cw[cv][co][R] (R = ci*5+k, 1280) -> g_wt2[cv][R][co] splatted (w,w)
__global__ void k_wtT(const float* __restrict__ cw) {
    __shared__ float tile[32][33];
    int cv = blockIdx.z;
    int r0 = blockIdx.x * 32, c0 = blockIdx.y * 32;
    int tx = threadIdx.x, ty = threadIdx.y;
#pragma unroll
    for (int r = 0; r < 4; r++) {
        int co = c0 + ty + r*8;
        tile[ty + r*8][tx] = cw[((size_t)cv*CC + co)*1280 + r0 + tx];
    }
    __syncthreads();
#pragma unroll
    for (int r = 0; r < 4; r++) {
        int rr = r0 + ty + r*8;
        float w = tile[tx][ty + r*8];
        g_wt2[((size_t)cv*1280 + rr)*CC + c0 + tx] = make_float2(w, w);
    }
}

// ----------------- prep: tl conv1 transpose + all 32 CCBN gamma/beta (compensated f32) ---------
__global__ void k_prep(const float* __restrict__ tw1,
                       const float* __restrict__ spk, const float* __restrict__ noi,
                       const float* __restrict__ gw_all, const float* __restrict__ gb_all,
                       const float* __restrict__ bw_all, const float* __restrict__ bb_all,
                       const float* __restrict__ tgw, const float* __restrict__ tgb,
                       const float* __restrict__ tbw, const float* __restrict__ tbb) {
    int bid = blockIdx.x;
    int t = threadIdx.x;
    if (bid < PREP_WT1_BLOCKS) {
        int idx = bid * 256 + t;
        int co = idx & 255;
        int ci = idx >> 8;
        float w = tw1[co*CC + ci];
        g_wt1s[ci*CC + co] = make_float2(w, w);
    } else {
        int g  = bid - PREP_WT1_BLOCKS;  // [0, 512)
        int i  = g >> 4;           // ccbn index 0..31
        int b  = g & 15;
        int c  = t;
        __shared__ float cs[CONDN];
        cs[c] = (c < 128) ? spk[b*128 + c] : noi[b*128 + (c - 128)];
        __syncthreads();
        const float *gw, *gb, *bw, *bb;
        if (i < 30) { gw = gw_all + (size_t)i*CONDN*CC; gb = gb_all + i*CC;
                      bw = bw_all + (size_t)i*CONDN*CC; bb = bb_all + i*CC; }
        else { int j = i - 30; gw = tgw + (size_t)j*CONDN*CC; gb = tgb + j*CC;
               bw = tbw + (size_t)j*CONDN*CC; bb = tbb + j*CC; }
        float sg = 0.f, cg = 0.f, sb = 0.f, cb = 0.f;
#pragma unroll 4
        for (int d = 0; d < CONDN; ++d) {
            float cv = cs[d];
            comp_fma(cv, gw[d*CC + c], sg, cg);
            comp_fma(cv, bw[d*CC + c], sb, cb);
        }
        int o = (i*BB + b)*CC + c;
        float gam = (float)(1.0 + ((double)sg + (double)cg) + (double)gb[c]);
        float bet = (float)(((double)sb + (double)cb) + (double)bb[c]);
        g_gb[o] = make_float2(gam, bet);
    }
}

// ----------------- embedding gather + transpose + stats partials -----------------
__global__ void k_embed(const int* __restrict__ toks, const float* __restrict__ emb,
                        float* __restrict__ x) {
    __shared__ float tile[32][33];
    __shared__ int tks[32];
    int b  = blockIdx.z;
    int l0 = blockIdx.x * 32, c0 = blockIdx.y * 32;
    int tx = threadIdx.x, ty = threadIdx.y;
    if (ty == 0) tks[tx] = (l0 + tx < LL) ? toks[b*LL + l0 + tx] : 0;
    __syncthreads();
#pragma unroll
    for (int r = 0; r < 4; r++) {
        int lr = ty + r*8;
        if (l0 + lr < LL) tile[lr][tx] = emb[(size_t)tks[lr]*CC + c0 + tx];
    }
    __syncthreads();
    int p = b*19 + blockIdx.x;   // partial index in [0, 304)
#pragma unroll
    for (int r = 0; r < 4; r++) {
        int c = c0 + ty + r*8;
        int l = l0 + tx;
        float fv = 0.f;
        if (l < LL) {
            fv = tile[tx][ty + r*8];
            x[((size_t)b*CC + c)*LL + l] = fv;
        }
        double s = (double)fv, s2 = s * s;
#pragma unroll
        for (int off = 16; off; off >>= 1) {
            s  += __shfl_xor_sync(0xffffffffu, s,  off);
            s2 += __shfl_xor_sync(0xffffffffu, s2, off);
        }
        if (tx == 0) g_part[(size_t)c*NPMAX + p] = make_double2(s, s2);
    }
}

// ----------------- reduce partials -> (mu, rstd) float2 (320 threads, 1 double2/thread) --------
__global__ void k_statsB(int np) {
    int c = blockIdx.x, t = threadIdx.x;
    int lane = t & 31, w = t >> 5;   // 10 warps
    double s = 0.0, s2 = 0.0;
    if (t < np) {
        double2 v = g_part[(size_t)c*NPMAX + t];
        s = v.x; s2 = v.y;
    }
#pragma unroll
    for (int off = 16; off; off >>= 1) {
        s  += __shfl_xor_sync(0xffffffffu, s,  off);
        s2 += __shfl_xor_sync(0xffffffffu, s2, off);
    }
    __shared__ double sh1[10], sh2[10];
    if (lane == 0) { sh1[w] = s; sh2[w] = s2; }
    __syncthreads();
    if (t == 0) {
        double ss = sh1[0], ss2 = sh2[0];
#pragma unroll
        for (int i = 1; i < 10; i++) { ss += sh1[i]; ss2 += sh2[i]; }
        double mu  = ss * (1.0 / 9600.0);
        double var = ss2 * (1.0 / 9600.0) - mu * mu;
        g_mur[c] = make_float2((float)mu, (float)(1.0 / sqrt(var + 1e-5)));
    }
}

// ---------- fused CCBN -> ReLU -> dilated conv; f32x2 lanes = batch pair (b0,b1) ----------
// R8/R12 mainloop verbatim: 256 threads, 2 blocks/SM; warp-group `half` covers ci in
// [half*128, +128), combined via f32x2 smem reduction; thread tco owns co = tco and tco+128.
// Grid (38, 8) = 304 blocks = exactly 2/SM on 152 SMs (no tail wave).
// Staging uses float2 (mu,rstd) and (gamma,beta) loads. Optional fused featsT store.
template<int K, int DIL, bool RESID>
__global__ void __launch_bounds__(256, 2) k_conv(
    const float* __restrict__ yin, const float2* __restrict__ wt,
    const float* __restrict__ bias, const float2* __restrict__ gb_,
    const float* __restrict__ resid,
    float* __restrict__ out, float* __restrict__ ft)
{
    constexpr int HALO = ((K - 1) / 2) * DIL;
    constexpr int PR   = LT + 2 * HALO;
    extern __shared__ float smraw[];
    float2* xs2 = reinterpret_cast<float2*>(smraw);  // [CC][PR], (v_b0, v_b1)

    int b0 = blockIdx.y * 2, b1 = b0 + 1;
    int l0 = blockIdx.x * LT;
    int t   = threadIdx.x;
    int tco = t & 127;
    int half = t >> 7;

    // stage: CCBN-normalize + ReLU both batches; zero halo/padding = SAME padding
    for (int idx = t; idx < CC * PR; idx += 256) {
        int ci = idx / PR;
        int p  = idx - ci * PR;
        int gl = l0 + p - HALO;
        float v0 = 0.f, v1 = 0.f;
        if (gl >= 0 && gl < LL) {
            float2 mr  = g_mur[ci];
            float2 gb0 = gb_[b0*CC + ci];
            float2 gb1 = gb_[b1*CC + ci];
            float r0 = yin[(size_t)(b0*CC + ci)*LL + gl];
            float r1 = yin[(size_t)(b1*CC + ci)*LL + gl];
            v0 = fmaxf(fmaf((r0 - mr.x) * mr.y, gb0.x, gb0.y), 0.f);
            v1 = fmaxf(fmaf((r1 - mr.x) * mr.y, gb1.x, gb1.y), 0.f);
        }
        xs2[idx] = make_float2(v0, v1);
    }
    __syncthreads();

    unsigned long long acc[2][LT];
    if (half == 0) {
        float bj0 = bias[tco], bj1 = bias[tco + 128];
        unsigned long long p0 = pk(bj0, bj0), p1 = pk(bj1, bj1);
#pragma unroll
        for (int l = 0; l < LT; l++) { acc[0][l] = p0; acc[1][l] = p1; }
    } else {
#pragma unroll
        for (int l = 0; l < LT; l++) { acc[0][l] = 0ull; acc[1][l] = 0ull; }
    }

    int cbeg = half * 128;
    const unsigned long long* wp64 =
        reinterpret_cast<const unsigned long long*>(wt);

#pragma unroll 2
    for (int cii = 0; cii < 128; ++cii) {
        int ci = cbeg + cii;
        unsigned long long wk0[K], wk1[K];
#pragma unroll
        for (int k = 0; k < K; k++) {
            wk0[k] = wp64[((size_t)ci*K + k)*CC + tco];
            wk1[k] = wp64[((size_t)ci*K + k)*CC + tco + 128];
        }
        const unsigned long long* xr =
            reinterpret_cast<const unsigned long long*>(xs2 + ci * PR);
#pragma unroll
        for (int p = 0; p < PR; p++) {
            unsigned long long xv = xr[p];
#pragma unroll
            for (int k = 0; k < K; k++) {
                int l = p - k * DIL;                 // compile-time folded
                if (l >= 0 && l < LT) {
                    fma2(acc[0][l], xv, wk0[k]);
                    fma2(acc[1][l], xv, wk1[k]);
                }
            }
        }
    }
    __syncthreads();   // xs2 dead; smem reused for reduction

    // combine halves: half 1 stores, half 0 adds (f32x2 adds)
    unsigned long long* red = reinterpret_cast<unsigned long long*>(smraw); // [2][128][LT]
    if (half == 1) {
#pragma unroll
        for (int j = 0; j < 2; j++)
#pragma unroll
            for (int l = 0; l < LT; l++)
                red[(j*128 + tco)*LT + l] = acc[j][l];
    }
    __syncthreads();
    if (half == 0) {
#pragma unroll
        for (int j = 0; j < 2; j++)
#pragma unroll
            for (int l = 0; l < LT; l++)
                acc[j][l] = add2(acc[j][l], red[(j*128 + tco)*LT + l]);
    }
    __syncthreads();   // red dead; smem reused for repack

    // repack to smem: rb[bi][co][l]  (2*256*16 floats = 32KB)
    float* rb = smraw;
    if (half == 0) {
#pragma unroll
        for (int l = 0; l < LT; l++) {
            float2 v0 = upk(acc[0][l]);   // co = tco
            float2 v1 = upk(acc[1][l]);   // co = tco + 128
            rb[(0*CC + tco)*LT + l]         = v0.x;
            rb[(1*CC + tco)*LT + l]         = v0.y;
            rb[(0*CC + tco + 128)*LT + l]   = v1.x;
            rb[(1*CC + tco + 128)*LT + l]   = v1.y;
        }
    }
    __syncthreads();

    // residual + coalesced store, guarded against ragged tail
#pragma unroll
    for (int bi = 0; bi < 2; bi++) {
        int bb = b0 + bi;
        for (int idx = t; idx < CC * LT; idx += 256) {
            int co = idx / LT, l = idx - co * LT;
            if (l0 + l >= LL) continue;
            size_t oa = (size_t)(bb*CC + co)*LL + l0 + l;
            float v = rb[bi*CC*LT + idx];
            if (RESID) { v += resid[oa]; rb[bi*CC*LT + idx] = v; }
            out[oa] = v;
        }
    }
    if (RESID) __syncthreads();

    // optional coalesced featsT store (B,L,C) — only last conv passes ft
    if (ft != nullptr) {
#pragma unroll
        for (int bi = 0; bi < 2; bi++) {
            int bb = b0 + bi;
            for (int idx = t; idx < CC * LT; idx += 256) {
                int cq = idx & 255, l = idx >> 8;    // CC = 256
                if (l0 + l < LL)
                    ft[((size_t)bb*LL + l0 + l)*CC + cq] = rb[(bi*CC + cq)*LT + l];
            }
        }
    }

    // stats partials (f64): thread t owns channel t; skip padded columns
    int pidx = blockIdx.y * NLT + blockIdx.x;   // [0, 304)
    {
        int ch = t;
        double s = 0.0, s2 = 0.0;
#pragma unroll
        for (int bi = 0; bi < 2; bi++)
#pragma unroll
            for (int l = 0; l < LT; l++) {
                if (l0 + l >= LL) continue;
                double v = (double)rb[(bi*CC + ch)*LT + l];
                s += v; s2 += v * v;
            }
        g_part[(size_t)ch*NPMAX + pidx] = make_double2(s, s2);
    }
}

// ------- TokenLength second conv (256->1, CCBN+ReLU fused, f64 accum) + parallel cumsum -------
__global__ void k_tl2(const float* __restrict__ tin, const float* __restrict__ w2,
                      const float* __restrict__ b2, const float2* __restrict__ gb_,
                      float* __restrict__ outlen, float* __restrict__ cent) {
    int b = blockIdx.x, t = threadIdx.x;
    __shared__ float ws[CC], gs[CC], bs[CC], mus[CC], rs[CC];
    __shared__ float tlbuf[LL];
    __shared__ double dsum[256];
    float2 gb0 = gb_[b*CC + t];
    float2 mr  = g_mur[t];
    ws[t] = w2[t]; gs[t] = gb0.x; bs[t] = gb0.y;
    mus[t] = mr.x; rs[t] = mr.y;
    __syncthreads();
    double bias2 = (double)b2[0];
    for (int l = t; l < LL; l += 256) {
        double s = bias2;
#pragma unroll 4
        for (int ci = 0; ci < CC; ci++) {
            float v = tin[(size_t)(b*CC + ci)*LL + l];
            v = fmaxf(fmaf((v - mus[ci]) * rs[ci], gs[ci], bs[ci]), 0.f);
            s += (double)ws[ci] * (double)v;
        }
        tlbuf[l] = fmaxf((float)s, 0.f);
    }
    __syncthreads();

    // parallel f64 cumsum: chunk of 3 per thread + Hillis-Steele scan of chunk sums
    const int CHK = 3;   // 256*3 = 768 >= 600
    int lbeg = t * CHK;
    double csum = 0.0;
#pragma unroll
    for (int j = 0; j < CHK; j++) {
        int l = lbeg + j;
        if (l < LL) csum += (double)tlbuf[l];
    }
    dsum[t] = csum;
    __syncthreads();
    for (int off = 1; off < 256; off <<= 1) {
        double v = dsum[t];
        double a = (t >= off) ? dsum[t - off] : 0.0;
        __syncthreads();
        dsum[t] = v + a;
        __syncthreads();
    }
    double run = (t > 0) ? dsum[t - 1] : 0.0;
#pragma unroll
    for (int j = 0; j < CHK; j++) {
        int l = lbeg + j;
        if (l < LL) {
            double tl = (double)tlbuf[l];
            run += tl;
            outlen[b*LL + l] = (float)run;
            cent[b*LL + l]   = (float)(run - 0.5 * tl);
        }
    }
}

// ----------------- alignment: windowed softmax(-(center-o)^2/10) @ feats (R12 exact) ----------
__global__ void __launch_bounds__(128) k_align(const float* __restrict__ featsT,
                                               const float* __restrict__ centers,
                                               float* __restrict__ outf) {
    extern __shared__ float smraw2[];
    float2* p2   = reinterpret_cast<float2*>(smraw2);   // [OT][LL] splatted weights
    float*  cen  = smraw2 + 2*OT*LL;
    float*  sinv = cen + LL;
    __shared__ int slo[OT], shi[OT];
    __shared__ int sLmin, sLmax;

    int b  = blockIdx.y;
    int o0 = blockIdx.x * OT;
    int t    = threadIdx.x;
    int lane = t & 31, wid = t >> 5;

    for (int i = t; i < LL; i += 128) cen[i] = centers[b*LL + i];
    __syncthreads();

    // per-o window via binary search (threads 0..OT-1)
    if (t < OT) {
        float of = (float)(o0 + t);
        int lo = 0, hi = LL;
        while (lo < hi) { int md = (lo + hi) >> 1; if (cen[md] < of) lo = md + 1; else hi = md; }
        float dmin = 3.4e38f;
        if (lo < LL) dmin = fabsf(cen[lo] - of);
        if (lo > 0)  dmin = fminf(dmin, fabsf(cen[lo - 1] - of));
        float R = sqrtf(fmaf(dmin, dmin, 700.0f));
        float xl = of - R, xr = of + R;
        int a = 0, bnd = LL;
        while (a < bnd) { int md = (a + bnd) >> 1; if (cen[md] < xl) a = md + 1; else bnd = md; }
        int wlo = a;
        a = 0; bnd = LL;
        while (a < bnd) { int md = (a + bnd) >> 1; if (cen[md] <= xr) a = md + 1; else bnd = md; }
        int whi = a - 1;
        if (whi < wlo) { wlo = (lo < LL) ? lo : LL - 1; whi = wlo; }  // safety: closest center
        slo[t] = wlo; shi[t] = whi;
    }
    __syncthreads();
    if (t == 0) {
        int mn = slo[0], mx = shi[0];
#pragma unroll
        for (int i = 1; i < OT; i++) { mn = min(mn, slo[i]); mx = max(mx, shi[i]); }
        sLmin = mn; sLmax = mx;
    }
    __syncthreads();
    int Lmin = sLmin, Lmax = sLmax;

    // phase A: per-o max-subtracted exp + sum over [lo, hi]; zero rest of union range
    for (int oo = wid; oo < OT; oo += 4) {
        float of = (float)(o0 + oo);
        int lo = slo[oo], hi = shi[oo];
        for (int l = Lmin + lane; l <= Lmax; l += 32)
            if (l < lo || l > hi) p2[oo*LL + l] = make_float2(0.f, 0.f);
        float m = -3.4e38f;
        for (int l = lo + lane; l <= hi; l += 32) {
            float d = cen[l] - of;
            float li = __fdiv_rn(-(d*d), 10.0f);
            m = fmaxf(m, li);
        }
#pragma unroll
        for (int s = 16; s; s >>= 1) m = fmaxf(m, __shfl_xor_sync(0xffffffffu, m, s));
        float ssum = 0.f;
        for (int l = lo + lane; l <= hi; l += 32) {
            float d = cen[l] - of;
            float li = __fdiv_rn(-(d*d), 10.0f);
            float e = expf(li - m);
            p2[oo*LL + l] = make_float2(e, e);
            ssum += e;
        }
#pragma unroll
        for (int s = 16; s; s >>= 1) ssum += __shfl_xor_sync(0xffffffffu, ssum, s);
        if (lane == 0) sinv[oo] = 1.0f / ssum;
    }
    __syncthreads();

    // phase B: out[o, c] = (sum_{l in union} w[o][l] * feats[l][c]) * sinv[o]
    int tc = t & 63, to = t >> 6;
    int ob = to * (OT/2);
    unsigned long long acc[OT/2][2];
#pragma unroll
    for (int j = 0; j < OT/2; j++) { acc[j][0] = 0ull; acc[j][1] = 0ull; }

    const unsigned long long* pw = reinterpret_cast<const unsigned long long*>(p2);
#pragma unroll 2
    for (int l = Lmin; l <= Lmax; ++l) {
        const unsigned long long* fp =
            reinterpret_cast<const unsigned long long*>(featsT + ((size_t)b*LL + l)*CC);
        unsigned long long f0 = fp[tc];
        unsigned long long f1 = fp[64 + tc];
#pragma unroll
        for (int j = 0; j < OT/2; ++j) {
            unsigned long long w = pw[(ob + j)*LL + l];
            fma2(acc[j][0], f0, w);
            fma2(acc[j][1], f1, w);
        }
    }
#pragma unroll
    for (int j = 0; j < OT/2; ++j) {
        float si = sinv[ob + j];
        size_t base = ((size_t)b*OUTS + o0 + ob + j)*CC;
        float2 v0 = upk(acc[j][0]); v0.x *= si; v0.y *= si;
        float2 v1 = upk(acc[j][1]); v1.x *= si; v1.y *= si;
        *reinterpret_cast<float2*>(&outf[base + 2*tc])        = v0;
        *reinterpret_cast<float2*>(&outf[base + 128 + 2*tc])  = v1;
    }
}

// ----------------- host launch -----------------
extern "C" void kernel_launch(void* const* d_in, const int* in_sizes, int n_in,
                              void* d_out, int out_size) {
    const int*   toks   = (const int*)  d_in[0];
    const float* spk    = (const float*)d_in[1];
    const float* noi    = (const float*)d_in[2];
    const float* emb    = (const float*)d_in[3];
    const float* conv_w = (const float*)d_in[4];
    const float* conv_b = (const float*)d_in[5];
    const float* g_w_   = (const float*)d_in[6];
    const float* g_b_   = (const float*)d_in[7];
    const float* b_w_   = (const float*)d_in[8];
    const float* b_b_   = (const float*)d_in[9];
    const float* tl_g_w = (const float*)d_in[10];
    const float* tl_g_b = (const float*)d_in[11];
    const float* tl_b_w = (const float*)d_in[12];
    const float* tl_b_b = (const float*)d_in[13];
    const float* tl_c1w = (const float*)d_in[14];
    const float* tl_c1b = (const float*)d_in[15];
    const float* tl_c2w = (const float*)d_in[16];
    const float* tl_c2b = (const float*)d_in[17];

    float* out_feat = (float*)d_out;
    float* out_len  = out_feat + (size_t)BB*OUTS*CC;

    float *px, *pt0, *pt1, *pft, *pcen;
    float2 *pwt2, *pwt1s, *pgb;
    cudaGetSymbolAddress((void**)&px,    g_x);
    cudaGetSymbolAddress((void**)&pt0,   g_t0);
    cudaGetSymbolAddress((void**)&pt1,   g_t1);
    cudaGetSymbolAddress((void**)&pwt2,  g_wt2);
    cudaGetSymbolAddress((void**)&pwt1s, g_wt1s);
    cudaGetSymbolAddress((void**)&pgb,   g_gb);
    cudaGetSymbolAddress((void**)&pft,   g_featsT);
    cudaGetSymbolAddress((void**)&pcen,  g_centers);

    // dynamic smem sizes (stage float2 tile; reduction/repack need 32KB <= all)
    const int sm_d1 = CC * (LT + 4)  * 8;   // 40960
    const int sm_d2 = CC * (LT + 8)  * 8;   // 49152
    const int sm_d4 = CC * (LT + 16) * 8;   // 65536
    const int sm_k1 = CC * LT        * 8;   // 32768
    const int sm_al = (2*OT*LL + LL + OT) * 4;  // 98480

    cudaFuncSetAttribute(k_conv<5,4,true>,  cudaFuncAttributeMaxDynamicSharedMemorySize, sm_d4);
    cudaFuncSetAttribute(k_conv<5,2,false>, cudaFuncAttributeMaxDynamicSharedMemorySize, sm_d2);
    cudaFuncSetAttribute(k_align,           cudaFuncAttributeMaxDynamicSharedMemorySize, sm_al);

    k_wtT<<<dim3(40, 8, NBLK*3), dim3(32, 8)>>>(conv_w);
    k_prep<<<PREP_TOTAL, 256>>>(tl_c1w, spk, noi, g_w_, g_b_, b_w_, b_b_,
                                tl_g_w, tl_g_b, tl_b_w, tl_b_b);
    {
        dim3 gb(19, 8, BB), tb(32, 8);
        k_embed<<<gb, tb>>>(toks, emb, px);
    }
    k_statsB<<<CC, 320>>>(19 * BB);   // 304 partials from embed

    dim3 cgrid(NLT, BB/2);            // (38, 8) = 304 blocks = 2/SM on 152 SMs
    for (int blk = 0; blk < NBLK; ++blk) {
        int c0 = blk*3 + 0, c1 = blk*3 + 1, c2 = blk*3 + 2;
        k_conv<5,1,false><<<cgrid, 256, sm_d1>>>(
            px,  pwt2 + (size_t)c0*5*CC*CC, conv_b + c0*CC,
            pgb + (size_t)c0*BB*CC, nullptr, pt0, nullptr);
        k_statsB<<<CC, 320>>>(NPMAX);
        k_conv<5,2,false><<<cgrid, 256, sm_d2>>>(
            pt0, pwt2 + (size_t)c1*5*CC*CC, conv_b + c1*CC,
            pgb + (size_t)c1*BB*CC, nullptr, pt1, nullptr);
        k_statsB<<<CC, 320>>>(NPMAX);
        k_conv<5,4,true><<<cgrid, 256, sm_d4>>>(
            pt1, pwt2 + (size_t)c2*5*CC*CC, conv_b + c2*CC,
            pgb + (size_t)c2*BB*CC, px, px,
            (blk == NBLK-1) ? pft : nullptr);
        k_statsB<<<CC, 320>>>(NPMAX);
    }

    // TokenLength head (x stats already current from last conv's partials)
    k_conv<1,1,false><<<cgrid, 256, sm_k1>>>(
        px, pwt1s, tl_c1b, pgb + (size_t)30*BB*CC, nullptr, pt0, nullptr);
    k_statsB<<<CC, 320>>>(NPMAX);
    k_tl2<<<BB, 256>>>(pt0, tl_c2w, tl_c2b, pgb + (size_t)31*BB*CC,
                       out_len, pcen);

    // alignment (featsT already written by last conv epilogue)
    k_align<<<dim3(OUTS/OT, BB), 128, sm_al>>>(pft, pcen, out_feat);
}

// round 16
// speedup vs baseline: 1.0223x; 1.0223x over previous
#include <cuda_runtime.h>
#include <math.h>

#define BB    16
#define LL    600
#define CC    256
#define OUTS  6000
#define NBLK  10
#define CONDN 256
#define LT    16      // conv output cols per block (38 tiles, last ragged)
#define NLT   38
#define OT    20      // align o's per block (6000 = 300*20)
#define NCCBN 32
#define NPMAX 304
#define BCL   (BB*CC*LL)

// prep kernel partition (wt1 + gamma/beta; conv weights in k_wtT)
#define PREP_WT1_BLOCKS  ((CC*CC) / 256)                    // 256
#define PREP_GB_BLOCKS   (NCCBN * BB)                       // 512
#define PREP_TOTAL       (PREP_WT1_BLOCKS + PREP_GB_BLOCKS)

// ----------------- static device scratch (no allocations allowed) -----------------
__device__ __align__(16) float g_x[BCL];
__device__ __align__(16) float g_t0[BCL];
__device__ __align__(16) float g_t1[BCL];
// [conv][ci][k][tco 0..127]: (w[tco], w[tco], w[tco+128], w[tco+128])
__device__ __align__(16) float4 g_wt4[NBLK*3*5*CC*128];
__device__ __align__(16) float4 g_wt1s4[CC*128];        // tl conv1, same float4 layout
__device__ __align__(16) float g_gamma[NCCBN*BB*CC];
__device__ __align__(16) float g_beta[NCCBN*BB*CC];
__device__ __align__(16) double2 g_part[CC*NPMAX];      // per-(channel, block) partial (sum, sumsq)
__device__ float g_mu[CC];
__device__ float g_rstd[CC];
__device__ float g_centers[BB*LL];
__device__ __align__(16) float g_featsT[BB*LL*CC];

// ----------------- f32x2 helpers -----------------
__device__ __forceinline__ unsigned long long pk(float lo, float hi) {
    unsigned long long r;
    asm("mov.b64 %0, {%1,%2};" : "=l"(r) : "f"(lo), "f"(hi));
    return r;
}
__device__ __forceinline__ float2 upk(unsigned long long v) {
    float2 r;
    asm("mov.b64 {%0,%1}, %2;" : "=f"(r.x), "=f"(r.y) : "l"(v));
    return r;
}
__device__ __forceinline__ void fma2(unsigned long long& d, unsigned long long a,
                                     unsigned long long b) {
    asm("fma.rn.f32x2 %0, %1, %2, %0;" : "+l"(d) : "l"(a), "l"(b));
}
__device__ __forceinline__ unsigned long long add2(unsigned long long a,
                                                   unsigned long long b) {
    unsigned long long r;
    asm("add.rn.f32x2 %0, %1, %2;" : "=l"(r) : "l"(a), "l"(b));
    return r;
}

// compensated accumulate: s += (a*b) exactly split via TwoProdFMA + branchless 2Sum
__device__ __forceinline__ void comp_fma(float a, float b, float& s, float& c) {
    float p = __fmul_rn(a, b);
    float e = fmaf(a, b, -p);          // exact product error
    float t  = s + p;
    float bp = t - s;
    c += (s - (t - bp)) + (p - bp);    // 2Sum error
    c += e;
    s = t;
}

// ----------------- conv weight transpose -> float4 layout (coalesced via smem tile) ------------
// cw[cv][co][R] (R = ci*5+k, 1280) -> g_wt4[cv][R][co&127] halves (.xy for co<128, .zw else)
__global__ void k_wtT(const float* __restrict__ cw) {
    __shared__ float tile[32][33];
    int cv = blockIdx.z;
    int r0 = blockIdx.x * 32, c0 = blockIdx.y * 32;
    int tx = threadIdx.x, ty = threadIdx.y;
#pragma unroll
    for (int r = 0; r < 4; r++) {
        int co = c0 + ty + r*8;
        tile[ty + r*8][tx] = cw[((size_t)cv*CC + co)*1280 + r0 + tx];
    }
    __syncthreads();
#pragma unroll
    for (int r = 0; r < 4; r++) {
        int rr = r0 + ty + r*8;
        int co = c0 + tx;
        float w = tile[tx][ty + r*8];
        float* dst = reinterpret_cast<float*>(
            &g_wt4[((size_t)cv*1280 + rr)*128 + (co & 127)]);
        *reinterpret_cast<float2*>(dst + ((co >= 128) ? 2 : 0)) = make_float2(w, w);
    }
}

// ----------------- prep: tl conv1 transpose (float4) + all 32 CCBN gamma/beta ------------------
__global__ void k_prep(const float* __restrict__ tw1,
                       const float* __restrict__ spk, const float* __restrict__ noi,
                       const float* __restrict__ gw_all, const float* __restrict__ gb_all,
                       const float* __restrict__ bw_all, const float* __restrict__ bb_all,
                       const float* __restrict__ tgw, const float* __restrict__ tgb,
                       const float* __restrict__ tbw, const float* __restrict__ tbb) {
    int bid = blockIdx.x;
    int t = threadIdx.x;
    if (bid < PREP_WT1_BLOCKS) {
        int idx = bid * 256 + t;
        int co = idx & 255;
        int ci = idx >> 8;
        float w = tw1[co*CC + ci];
        float* dst = reinterpret_cast<float*>(&g_wt1s4[(size_t)ci*128 + (co & 127)]);
        *reinterpret_cast<float2*>(dst + ((co >= 128) ? 2 : 0)) = make_float2(w, w);
    } else {
        int g  = bid - PREP_WT1_BLOCKS;  // [0, 512)
        int i  = g >> 4;           // ccbn index 0..31
        int b  = g & 15;
        int c  = t;
        __shared__ float cs[CONDN];
        cs[c] = (c < 128) ? spk[b*128 + c] : noi[b*128 + (c - 128)];
        __syncthreads();
        const float *gw, *gb, *bw, *bb;
        if (i < 30) { gw = gw_all + (size_t)i*CONDN*CC; gb = gb_all + i*CC;
                      bw = bw_all + (size_t)i*CONDN*CC; bb = bb_all + i*CC; }
        else { int j = i - 30; gw = tgw + (size_t)j*CONDN*CC; gb = tgb + j*CC;
               bw = tbw + (size_t)j*CONDN*CC; bb = tbb + j*CC; }
        float sg = 0.f, cg = 0.f, sb = 0.f, cb = 0.f;
#pragma unroll 4
        for (int d = 0; d < CONDN; ++d) {
            float cv = cs[d];
            comp_fma(cv, gw[d*CC + c], sg, cg);
            comp_fma(cv, bw[d*CC + c], sb, cb);
        }
        int o = (i*BB + b)*CC + c;
        g_gamma[o] = (float)(1.0 + ((double)sg + (double)cg) + (double)gb[c]);
        g_beta[o]  = (float)(((double)sb + (double)cb) + (double)bb[c]);
    }
}

// ----------------- embedding gather + transpose + stats partials -----------------
__global__ void k_embed(const int* __restrict__ toks, const float* __restrict__ emb,
                        float* __restrict__ x) {
    __shared__ float tile[32][33];
    __shared__ int tks[32];
    int b  = blockIdx.z;
    int l0 = blockIdx.x * 32, c0 = blockIdx.y * 32;
    int tx = threadIdx.x, ty = threadIdx.y;
    if (ty == 0) tks[tx] = (l0 + tx < LL) ? toks[b*LL + l0 + tx] : 0;
    __syncthreads();
#pragma unroll
    for (int r = 0; r < 4; r++) {
        int lr = ty + r*8;
        if (l0 + lr < LL) tile[lr][tx] = emb[(size_t)tks[lr]*CC + c0 + tx];
    }
    __syncthreads();
    int p = b*19 + blockIdx.x;   // partial index in [0, 304)
#pragma unroll
    for (int r = 0; r < 4; r++) {
        int c = c0 + ty + r*8;
        int l = l0 + tx;
        float fv = 0.f;
        if (l < LL) {
            fv = tile[tx][ty + r*8];
            x[((size_t)b*CC + c)*LL + l] = fv;
        }
        double s = (double)fv, s2 = s * s;
#pragma unroll
        for (int off = 16; off; off >>= 1) {
            s  += __shfl_xor_sync(0xffffffffu, s,  off);
            s2 += __shfl_xor_sync(0xffffffffu, s2, off);
        }
        if (tx == 0) g_part[(size_t)c*NPMAX + p] = make_double2(s, s2);
    }
}

// ----------------- reduce partials -> mu / rstd (320 threads, 1 double2/thread) ---------------
__global__ void k_statsB(int np) {
    int c = blockIdx.x, t = threadIdx.x;
    int lane = t & 31, w = t >> 5;   // 10 warps
    double s = 0.0, s2 = 0.0;
    if (t < np) {
        double2 v = g_part[(size_t)c*NPMAX + t];
        s = v.x; s2 = v.y;
    }
#pragma unroll
    for (int off = 16; off; off >>= 1) {
        s  += __shfl_xor_sync(0xffffffffu, s,  off);
        s2 += __shfl_xor_sync(0xffffffffu, s2, off);
    }
    __shared__ double sh1[10], sh2[10];
    if (lane == 0) { sh1[w] = s; sh2[w] = s2; }
    __syncthreads();
    if (t == 0) {
        double ss = sh1[0], ss2 = sh2[0];
#pragma unroll
        for (int i = 1; i < 10; i++) { ss += sh1[i]; ss2 += sh2[i]; }
        double mu  = ss * (1.0 / 9600.0);
        double var = ss2 * (1.0 / 9600.0) - mu * mu;
        g_mu[c]   = (float)mu;
        g_rstd[c] = (float)(1.0 / sqrt(var + 1e-5));
    }
}

// ---------- fused CCBN -> ReLU -> dilated conv; f32x2 lanes = batch pair (b0,b1) ----------
// R14 structure; operand streams vectorized: weights LDG.128 (float4 pairs), inputs LDS.128.
// 256 threads, 2 blocks/SM; warp-group `half` covers ci in [half*128, +128); thread tco owns
// co = tco and tco+128. Grid (38, 8) = 304 blocks = 2/SM on 152 SMs.
template<int K, int DIL, bool RESID>
__global__ void __launch_bounds__(256, 2) k_conv(
    const float* __restrict__ yin, const float4* __restrict__ wt,
    const float* __restrict__ bias, const float* __restrict__ gamma,
    const float* __restrict__ beta, const float* __restrict__ resid,
    float* __restrict__ out, float* __restrict__ ft)
{
    constexpr int HALO = ((K - 1) / 2) * DIL;
    constexpr int PR   = LT + 2 * HALO;   // even for all instantiations
    extern __shared__ float smraw[];
    float2* xs2 = reinterpret_cast<float2*>(smraw);  // [CC][PR], (v_b0, v_b1)

    int b0 = blockIdx.y * 2, b1 = b0 + 1;
    int l0 = blockIdx.x * LT;
    int t   = threadIdx.x;
    int tco = t & 127;
    int half = t >> 7;

    // stage: CCBN-normalize + ReLU both batches; zero halo/padding = SAME padding
    for (int idx = t; idx < CC * PR; idx += 256) {
        int ci = idx / PR;
        int p  = idx - ci * PR;
        int gl = l0 + p - HALO;
        float v0 = 0.f, v1 = 0.f;
        if (gl >= 0 && gl < LL) {
            float mu = g_mu[ci], rs = g_rstd[ci];
            float r0 = yin[(size_t)(b0*CC + ci)*LL + gl];
            float r1 = yin[(size_t)(b1*CC + ci)*LL + gl];
            v0 = fmaxf(fmaf((r0 - mu) * rs, gamma[b0*CC + ci], beta[b0*CC + ci]), 0.f);
            v1 = fmaxf(fmaf((r1 - mu) * rs, gamma[b1*CC + ci], beta[b1*CC + ci]), 0.f);
        }
        xs2[idx] = make_float2(v0, v1);
    }
    __syncthreads();

    unsigned long long acc[2][LT];
    if (half == 0) {
        float bj0 = bias[tco], bj1 = bias[tco + 128];
        unsigned long long p0 = pk(bj0, bj0), p1 = pk(bj1, bj1);
#pragma unroll
        for (int l = 0; l < LT; l++) { acc[0][l] = p0; acc[1][l] = p1; }
    } else {
#pragma unroll
        for (int l = 0; l < LT; l++) { acc[0][l] = 0ull; acc[1][l] = 0ull; }
    }

    int cbeg = half * 128;
    const ulonglong2* wp = reinterpret_cast<const ulonglong2*>(wt);

#pragma unroll 2
    for (int cii = 0; cii < 128; ++cii) {
        int ci = cbeg + cii;
        unsigned long long wk0[K], wk1[K];
#pragma unroll
        for (int k = 0; k < K; k++) {
            ulonglong2 w2 = wp[((size_t)ci*K + k)*128 + tco];  // LDG.128
            wk0[k] = w2.x;   // (w[tco], w[tco])
            wk1[k] = w2.y;   // (w[tco+128], w[tco+128])
        }
        const unsigned long long* xr =
            reinterpret_cast<const unsigned long long*>(xs2 + ci * PR);
#pragma unroll
        for (int p = 0; p < PR; p += 2) {
            ulonglong2 xv2 = *reinterpret_cast<const ulonglong2*>(xr + p);  // LDS.128
#pragma unroll
            for (int k = 0; k < K; k++) {
                int l = p - k * DIL;                 // compile-time folded
                if (l >= 0 && l < LT) {
                    fma2(acc[0][l], xv2.x, wk0[k]);
                    fma2(acc[1][l], xv2.x, wk1[k]);
                }
            }
#pragma unroll
            for (int k = 0; k < K; k++) {
                int l = p + 1 - k * DIL;
                if (l >= 0 && l < LT) {
                    fma2(acc[0][l], xv2.y, wk0[k]);
                    fma2(acc[1][l], xv2.y, wk1[k]);
                }
            }
        }
    }
    __syncthreads();   // xs2 dead; smem reused for reduction

    // combine halves: half 1 stores, half 0 adds (f32x2 adds)
    unsigned long long* red = reinterpret_cast<unsigned long long*>(smraw); // [2][128][LT]
    if (half == 1) {
#pragma unroll
        for (int j = 0; j < 2; j++)
#pragma unroll
            for (int l = 0; l < LT; l++)
                red[(j*128 + tco)*LT + l] = acc[j][l];
    }
    __syncthreads();
    if (half == 0) {
#pragma unroll
        for (int j = 0; j < 2; j++)
#pragma unroll
            for (int l = 0; l < LT; l++)
                acc[j][l] = add2(acc[j][l], red[(j*128 + tco)*LT + l]);
    }
    __syncthreads();   // red dead; smem reused for repack

    // repack to smem: rb[bi][co][l]  (2*256*16 floats = 32KB)
    float* rb = smraw;
    if (half == 0) {
#pragma unroll
        for (int l = 0; l < LT; l++) {
            float2 v0 = upk(acc[0][l]);   // co = tco
            float2 v1 = upk(acc[1][l]);   // co = tco + 128
            rb[(0*CC + tco)*LT + l]         = v0.x;
            rb[(1*CC + tco)*LT + l]         = v0.y;
            rb[(0*CC + tco + 128)*LT + l]   = v1.x;
            rb[(1*CC + tco + 128)*LT + l]   = v1.y;
        }
    }
    __syncthreads();

    // residual + coalesced store, guarded against ragged tail
#pragma unroll
    for (int bi = 0; bi < 2; bi++) {
        int bb = b0 + bi;
        for (int idx = t; idx < CC * LT; idx += 256) {
            int co = idx / LT, l = idx - co * LT;
            if (l0 + l >= LL) continue;
            size_t oa = (size_t)(bb*CC + co)*LL + l0 + l;
            float v = rb[bi*CC*LT + idx];
            if (RESID) { v += resid[oa]; rb[bi*CC*LT + idx] = v; }
            out[oa] = v;
        }
    }
    if (RESID) __syncthreads();

    // optional coalesced featsT store (B,L,C) — only last conv passes ft
    if (ft != nullptr) {
#pragma unroll
        for (int bi = 0; bi < 2; bi++) {
            int bb = b0 + bi;
            for (int idx = t; idx < CC * LT; idx += 256) {
                int cq = idx & 255, l = idx >> 8;    // CC = 256
                if (l0 + l < LL)
                    ft[((size_t)bb*LL + l0 + l)*CC + cq] = rb[(bi*CC + cq)*LT + l];
            }
        }
    }

    // stats partials (f64): thread t owns channel t; skip padded columns
    int pidx = blockIdx.y * NLT + blockIdx.x;   // [0, 304)
    {
        int ch = t;
        double s = 0.0, s2 = 0.0;
#pragma unroll
        for (int bi = 0; bi < 2; bi++)
#pragma unroll
            for (int l = 0; l < LT; l++) {
                if (l0 + l >= LL) continue;
                double v = (double)rb[(bi*CC + ch)*LT + l];
                s += v; s2 += v * v;
            }
        g_part[(size_t)ch*NPMAX + pidx] = make_double2(s, s2);
    }
}

// ------- TokenLength second conv (256->1, CCBN+ReLU fused, f64 accum) + parallel cumsum -------
__global__ void k_tl2(const float* __restrict__ tin, const float* __restrict__ w2,
                      const float* __restrict__ b2, const float* __restrict__ gamma,
                      const float* __restrict__ beta, float* __restrict__ outlen,
                      float* __restrict__ cent) {
    int b = blockIdx.x, t = threadIdx.x;
    __shared__ float ws[CC], gs[CC], bs[CC], mus[CC], rs[CC];
    __shared__ float tlbuf[LL];
    __shared__ double dsum[256];
    ws[t] = w2[t]; gs[t] = gamma[b*CC + t]; bs[t] = beta[b*CC + t];
    mus[t] = g_mu[t]; rs[t] = g_rstd[t];
    __syncthreads();
    double bias2 = (double)b2[0];
    for (int l = t; l < LL; l += 256) {
        double s = bias2;
#pragma unroll 4
        for (int ci = 0; ci < CC; ci++) {
            float v = tin[(size_t)(b*CC + ci)*LL + l];
            v = fmaxf(fmaf((v - mus[ci]) * rs[ci], gs[ci], bs[ci]), 0.f);
            s += (double)ws[ci] * (double)v;
        }
        tlbuf[l] = fmaxf((float)s, 0.f);
    }
    __syncthreads();

    // parallel f64 cumsum: chunk of 3 per thread + Hillis-Steele scan of chunk sums
    const int CHK = 3;   // 256*3 = 768 >= 600
    int lbeg = t * CHK;
    double csum = 0.0;
#pragma unroll
    for (int j = 0; j < CHK; j++) {
        int l = lbeg + j;
        if (l < LL) csum += (double)tlbuf[l];
    }
    dsum[t] = csum;
    __syncthreads();
    for (int off = 1; off < 256; off <<= 1) {
        double v = dsum[t];
        double a = (t >= off) ? dsum[t - off] : 0.0;
        __syncthreads();
        dsum[t] = v + a;
        __syncthreads();
    }
    double run = (t > 0) ? dsum[t - 1] : 0.0;
#pragma unroll
    for (int j = 0; j < CHK; j++) {
        int l = lbeg + j;
        if (l < LL) {
            double tl = (double)tlbuf[l];
            run += tl;
            outlen[b*LL + l] = (float)run;
            cent[b*LL + l]   = (float)(run - 0.5 * tl);
        }
    }
}

// ----------------- alignment: windowed softmax(-(center-o)^2/10) @ feats (R12 exact) ----------
__global__ void __launch_bounds__(128) k_align(const float* __restrict__ featsT,
                                               const float* __restrict__ centers,
                                               float* __restrict__ outf) {
    extern __shared__ float smraw2[];
    float2* p2   = reinterpret_cast<float2*>(smraw2);   // [OT][LL] splatted weights
    float*  cen  = smraw2 + 2*OT*LL;
    float*  sinv = cen + LL;
    __shared__ int slo[OT], shi[OT];
    __shared__ int sLmin, sLmax;

    int b  = blockIdx.y;
    int o0 = blockIdx.x * OT;
    int t    = threadIdx.x;
    int lane = t & 31, wid = t >> 5;

    for (int i = t; i < LL; i += 128) cen[i] = centers[b*LL + i];
    __syncthreads();

    // per-o window via binary search (threads 0..OT-1)
    if (t < OT) {
        float of = (float)(o0 + t);
        int lo = 0, hi = LL;
        while (lo < hi) { int md = (lo + hi) >> 1; if (cen[md] < of) lo = md + 1; else hi = md; }
        float dmin = 3.4e38f;
        if (lo < LL) dmin = fabsf(cen[lo] - of);
        if (lo > 0)  dmin = fminf(dmin, fabsf(cen[lo - 1] - of));
        float R = sqrtf(fmaf(dmin, dmin, 700.0f));
        float xl = of - R, xr = of + R;
        int a = 0, bnd = LL;
        while (a < bnd) { int md = (a + bnd) >> 1; if (cen[md] < xl) a = md + 1; else bnd = md; }
        int wlo = a;
        a = 0; bnd = LL;
        while (a < bnd) { int md = (a + bnd) >> 1; if (cen[md] <= xr) a = md + 1; else bnd = md; }
        int whi = a - 1;
        if (whi < wlo) { wlo = (lo < LL) ? lo : LL - 1; whi = wlo; }  // safety: closest center
        slo[t] = wlo; shi[t] = whi;
    }
    __syncthreads();
    if (t == 0) {
        int mn = slo[0], mx = shi[0];
#pragma unroll
        for (int i = 1; i < OT; i++) { mn = min(mn, slo[i]); mx = max(mx, shi[i]); }
        sLmin = mn; sLmax = mx;
    }
    __syncthreads();
    int Lmin = sLmin, Lmax = sLmax;

    // phase A: per-o max-subtracted exp + sum over [lo, hi]; zero rest of union range
    for (int oo = wid; oo < OT; oo += 4) {
        float of = (float)(o0 + oo);
        int lo = slo[oo], hi = shi[oo];
        for (int l = Lmin + lane; l <= Lmax; l += 32)
            if (l < lo || l > hi) p2[oo*LL + l] = make_float2(0.f, 0.f);
        float m = -3.4e38f;
        for (int l = lo + lane; l <= hi; l += 32) {
            float d = cen[l] - of;
            float li = __fdiv_rn(-(d*d), 10.0f);
            m = fmaxf(m, li);
        }
#pragma unroll
        for (int s = 16; s; s >>= 1) m = fmaxf(m, __shfl_xor_sync(0xffffffffu, m, s));
        float ssum = 0.f;
        for (int l = lo + lane; l <= hi; l += 32) {
            float d = cen[l] - of;
            float li = __fdiv_rn(-(d*d), 10.0f);
            float e = expf(li - m);
            p2[oo*LL + l] = make_float2(e, e);
            ssum += e;
        }
#pragma unroll
        for (int s = 16; s; s >>= 1) ssum += __shfl_xor_sync(0xffffffffu, ssum, s);
        if (lane == 0) sinv[oo] = 1.0f / ssum;
    }
    __syncthreads();

    // phase B: out[o, c] = (sum_{l in union} w[o][l] * feats[l][c]) * sinv[o]
    int tc = t & 63, to = t >> 6;
    int ob = to * (OT/2);
    unsigned long long acc[OT/2][2];
#pragma unroll
    for (int j = 0; j < OT/2; j++) { acc[j][0] = 0ull; acc[j][1] = 0ull; }

    const unsigned long long* pw = reinterpret_cast<const unsigned long long*>(p2);
#pragma unroll 2
    for (int l = Lmin; l <= Lmax; ++l) {
        const unsigned long long* fp =
            reinterpret_cast<const unsigned long long*>(featsT + ((size_t)b*LL + l)*CC);
        unsigned long long f0 = fp[tc];
        unsigned long long f1 = fp[64 + tc];
#pragma unroll
        for (int j = 0; j < OT/2; ++j) {
            unsigned long long w = pw[(ob + j)*LL + l];
            fma2(acc[j][0], f0, w);
            fma2(acc[j][1], f1, w);
        }
    }
#pragma unroll
    for (int j = 0; j < OT/2; ++j) {
        float si = sinv[ob + j];
        size_t base = ((size_t)b*OUTS + o0 + ob + j)*CC;
        float2 v0 = upk(acc[j][0]); v0.x *= si; v0.y *= si;
        float2 v1 = upk(acc[j][1]); v1.x *= si; v1.y *= si;
        *reinterpret_cast<float2*>(&outf[base + 2*tc])        = v0;
        *reinterpret_cast<float2*>(&outf[base + 128 + 2*tc])  = v1;
    }
}

// ----------------- host launch -----------------
extern "C" void kernel_launch(void* const* d_in, const int* in_sizes, int n_in,
                              void* d_out, int out_size) {
    const int*   toks   = (const int*)  d_in[0];
    const float* spk    = (const float*)d_in[1];
    const float* noi    = (const float*)d_in[2];
    const float* emb    = (const float*)d_in[3];
    const float* conv_w = (const float*)d_in[4];
    const float* conv_b = (const float*)d_in[5];
    const float* g_w_   = (const float*)d_in[6];
    const float* g_b_   = (const float*)d_in[7];
    const float* b_w_   = (const float*)d_in[8];
    const float* b_b_   = (const float*)d_in[9];
    const float* tl_g_w = (const float*)d_in[10];
    const float* tl_g_b = (const float*)d_in[11];
    const float* tl_b_w = (const float*)d_in[12];
    const float* tl_b_b = (const float*)d_in[13];
    const float* tl_c1w = (const float*)d_in[14];
    const float* tl_c1b = (const float*)d_in[15];
    const float* tl_c2w = (const float*)d_in[16];
    const float* tl_c2b = (const float*)d_in[17];

    float* out_feat = (float*)d_out;
    float* out_len  = out_feat + (size_t)BB*OUTS*CC;

    float *px, *pt0, *pt1, *pgam, *pbet, *pft, *pcen;
    float4 *pwt4, *pwt1s4;
    cudaGetSymbolAddress((void**)&px,     g_x);
    cudaGetSymbolAddress((void**)&pt0,    g_t0);
    cudaGetSymbolAddress((void**)&pt1,    g_t1);
    cudaGetSymbolAddress((void**)&pwt4,   g_wt4);
    cudaGetSymbolAddress((void**)&pwt1s4, g_wt1s4);
    cudaGetSymbolAddress((void**)&pgam,   g_gamma);
    cudaGetSymbolAddress((void**)&pbet,   g_beta);
    cudaGetSymbolAddress((void**)&pft,    g_featsT);
    cudaGetSymbolAddress((void**)&pcen,   g_centers);

    // dynamic smem sizes (stage float2 tile; reduction/repack need 32KB <= all)
    const int sm_d1 = CC * (LT + 4)  * 8;   // 40960
    const int sm_d2 = CC * (LT + 8)  * 8;   // 49152
    const int sm_d4 = CC * (LT + 16) * 8;   // 65536
    const int sm_k1 = CC * LT        * 8;   // 32768
    const int sm_al = (2*OT*LL + LL + OT) * 4;  // 98480

    cudaFuncSetAttribute(k_conv<5,4,true>,  cudaFuncAttributeMaxDynamicSharedMemorySize, sm_d4);
    cudaFuncSetAttribute(k_conv<5,2,false>, cudaFuncAttributeMaxDynamicSharedMemorySize, sm_d2);
    cudaFuncSetAttribute(k_align,           cudaFuncAttributeMaxDynamicSharedMemorySize, sm_al);

    k_wtT<<<dim3(40, 8, NBLK*3), dim3(32, 8)>>>(conv_w);
    k_prep<<<PREP_TOTAL, 256>>>(tl_c1w, spk, noi, g_w_, g_b_, b_w_, b_b_,
                                tl_g_w, tl_g_b, tl_b_w, tl_b_b);
    {
        dim3 gb(19, 8, BB), tb(32, 8);
        k_embed<<<gb, tb>>>(toks, emb, px);
    }
    k_statsB<<<CC, 320>>>(19 * BB);   // 304 partials from embed

    dim3 cgrid(NLT, BB/2);            // (38, 8) = 304 blocks = 2/SM on 152 SMs
    for (int blk = 0; blk < NBLK; ++blk) {
        int c0 = blk*3 + 0, c1 = blk*3 + 1, c2 = blk*3 + 2;
        k_conv<5,1,false><<<cgrid, 256, sm_d1>>>(
            px,  pwt4 + (size_t)c0*5*CC*128, conv_b + c0*CC,
            pgam + c0*BB*CC, pbet + c0*BB*CC, nullptr, pt0, nullptr);
        k_statsB<<<CC, 320>>>(NPMAX);
        k_conv<5,2,false><<<cgrid, 256, sm_d2>>>(
            pt0, pwt4 + (size_t)c1*5*CC*128, conv_b + c1*CC,
            pgam + c1*BB*CC, pbet + c1*BB*CC, nullptr, pt1, nullptr);
        k_statsB<<<CC, 320>>>(NPMAX);
        k_conv<5,4,true><<<cgrid, 256, sm_d4>>>(
            pt1, pwt4 + (size_t)c2*5*CC*128, conv_b + c2*CC,
            pgam + c2*BB*CC, pbet + c2*BB*CC, px, px,
            (blk == NBLK-1) ? pft : nullptr);
        k_statsB<<<CC, 320>>>(NPMAX);
    }

    // TokenLength head (x stats already current from last conv's partials)
    k_conv<1,1,false><<<cgrid, 256, sm_k1>>>(
        px, pwt1s4, tl_c1b, pgam + 30*BB*CC, pbet + 30*BB*CC, nullptr, pt0, nullptr);
    k_statsB<<<CC, 320>>>(NPMAX);
    k_tl2<<<BB, 256>>>(pt0, tl_c2w, tl_c2b, pgam + 31*BB*CC, pbet + 31*BB*CC,
                       out_len, pcen);

    // alignment (featsT already written by last conv epilogue)
    k_align<<<dim3(OUTS/OT, BB), 128, sm_al>>>(pft, pcen, out_feat);
}